// round 1
// baseline (speedup 1.0000x reference)
#include <cuda_runtime.h>
#include <math.h>

#define B_ 512
#define N_ 128
#define F_ 128
#define K_ 4
#define TI 32          // output rows per block in layer kernel
#define NT 4           // N_/TI i-tiles

// Scratch (device globals: allocation-free per harness rules)
__device__ float g_bufA[(size_t)B_ * N_ * F_];
__device__ float g_bufB[(size_t)B_ * N_ * F_];
__device__ float g_D[B_ * N_];
__device__ float g_part[B_];

// ---------------------------------------------------------------------------
// Degree norm: D[b,i] = 1 / (sum_{j,k} E[b,i,j,k] + K). One warp per row.
// ---------------------------------------------------------------------------
__global__ void deg_kernel(const float* __restrict__ E) {
    int warp = (blockIdx.x * blockDim.x + threadIdx.x) >> 5;
    int lane = threadIdx.x & 31;
    if (warp >= B_ * N_) return;
    const float* row = E + (size_t)warp * (N_ * K_);
    float s = 0.f;
    #pragma unroll 4
    for (int t = lane; t < N_ * K_; t += 32) s += row[t];
    #pragma unroll
    for (int o = 16; o > 0; o >>= 1) s += __shfl_xor_sync(0xffffffffu, s, o);
    if (lane == 0) g_D[warp] = 1.0f / (s + (float)K_);
}

// ---------------------------------------------------------------------------
// Fused RGCN layer. One block = (b, 32-row i-tile). 256 threads.
// smem: Hs[128][128] (64KB) | Ms[32][512] (64KB) | Us union (64KB) = 192KB
//   GEMM1: Ms[i][m*4+k] = sum_j E[b,i,j,k] * H[b,j,m]
//   GEMM2: msg[i][n]    = sum_{m,k} Ms[i][m*4+k] * RW[m,n,k]
//   Self : s[i][n]      = sum_j H[b,i,j] * SW[j,n]
//   out   = sigmoid(msg * D[b,i] + s)
// ---------------------------------------------------------------------------
extern __shared__ float smem[];

__global__ __launch_bounds__(256, 1) void layer_kernel(
    const float* __restrict__ E,
    const float* __restrict__ Hin,
    const float* __restrict__ RW,
    const float* __restrict__ SW,
    float* __restrict__ Hout)
{
    float* Hs = smem;               // 16384 floats
    float* Ms = smem + 16384;       // 16384 floats
    float* Us = smem + 32768;       // 16384 floats (E-tile / RW-tile / SW)

    const int b  = blockIdx.y;
    const int i0 = blockIdx.x * TI;
    const int tid = threadIdx.x;
    const int tx = tid & 31;        // n / m lane
    const int ty = tid >> 5;        // i group (0..7)

    // ---- Load H[b] (whole 128x128) into Hs ----
    {
        const float4* H4 = (const float4*)(Hin + (size_t)b * N_ * F_);
        float4* Hs4 = (float4*)Hs;
        #pragma unroll
        for (int l = tid; l < N_ * F_ / 4; l += 256) Hs4[l] = H4[l];
    }

    // ---- Load E tile rows [i0, i0+32), transpose to Us[k][i][j] ----
    {
        const float4* E4 = (const float4*)(E + ((size_t)b * N_ + i0) * (N_ * K_));
        #pragma unroll
        for (int l = tid; l < TI * N_; l += 256) {
            int i = l >> 7, j = l & 127;
            float4 v = E4[l];   // E[i][j][0..3]
            Us[0 * TI * N_ + i * N_ + j] = v.x;
            Us[1 * TI * N_ + i * N_ + j] = v.y;
            Us[2 * TI * N_ + i * N_ + j] = v.z;
            Us[3 * TI * N_ + i * N_ + j] = v.w;
        }
    }
    __syncthreads();

    // ---- GEMM1: per k, [32 x 128] @ [128 x 128] -> Ms[i][m*4+k] ----
    #pragma unroll
    for (int k = 0; k < K_; k++) {
        float acc[4][4];
        #pragma unroll
        for (int r = 0; r < 4; r++)
            #pragma unroll
            for (int c = 0; c < 4; c++) acc[r][c] = 0.f;

        const float* Ek = Us + k * TI * N_;
        #pragma unroll 4
        for (int j = 0; j < N_; j++) {
            float a[4], bb[4];
            #pragma unroll
            for (int r = 0; r < 4; r++) a[r] = Ek[(ty + 8 * r) * N_ + j];
            #pragma unroll
            for (int c = 0; c < 4; c++) bb[c] = Hs[j * F_ + tx + 32 * c];
            #pragma unroll
            for (int r = 0; r < 4; r++)
                #pragma unroll
                for (int c = 0; c < 4; c++) acc[r][c] = fmaf(a[r], bb[c], acc[r][c]);
        }
        #pragma unroll
        for (int r = 0; r < 4; r++)
            #pragma unroll
            for (int c = 0; c < 4; c++)
                Ms[(ty + 8 * r) * (F_ * K_) + (tx + 32 * c) * K_ + k] = acc[r][c];
    }
    __syncthreads();

    // ---- GEMM2: msg = Ms[32 x 512] @ RW[(m,k) x n], staged in 64-row tiles ----
    float accm[4][4];
    #pragma unroll
    for (int r = 0; r < 4; r++)
        #pragma unroll
        for (int c = 0; c < 4; c++) accm[r][c] = 0.f;

    for (int mt = 0; mt < 8; mt++) {
        __syncthreads();  // previous Us readers done
        {   // stage RW rows m in [mt*16, mt*16+16), all n, all k -> Us[(ml*4+k)][n]
            const float4* RW4 = (const float4*)RW;   // RW[m][n][0..3] per float4
            #pragma unroll
            for (int l = tid; l < 16 * 128; l += 256) {
                int ml = l >> 7, n = l & 127;
                float4 v = RW4[(size_t)(mt * 16 + ml) * 128 + n];
                Us[(ml * 4 + 0) * 128 + n] = v.x;
                Us[(ml * 4 + 1) * 128 + n] = v.y;
                Us[(ml * 4 + 2) * 128 + n] = v.z;
                Us[(ml * 4 + 3) * 128 + n] = v.w;
            }
        }
        __syncthreads();
        #pragma unroll 4
        for (int mk = 0; mk < 64; mk++) {
            float a[4], bb[4];
            #pragma unroll
            for (int r = 0; r < 4; r++) a[r] = Ms[(ty + 8 * r) * 512 + mt * 64 + mk];
            #pragma unroll
            for (int c = 0; c < 4; c++) bb[c] = Us[mk * 128 + tx + 32 * c];
            #pragma unroll
            for (int r = 0; r < 4; r++)
                #pragma unroll
                for (int c = 0; c < 4; c++) accm[r][c] = fmaf(a[r], bb[c], accm[r][c]);
        }
    }

    // ---- Self term: s = H[b, i0:i0+32, :] @ SW ----
    __syncthreads();
    {
        const float4* SW4 = (const float4*)SW;
        float4* Us4 = (float4*)Us;
        #pragma unroll
        for (int l = tid; l < N_ * F_ / 4; l += 256) Us4[l] = SW4[l];
    }
    __syncthreads();

    float accs[4][4];
    #pragma unroll
    for (int r = 0; r < 4; r++)
        #pragma unroll
        for (int c = 0; c < 4; c++) accs[r][c] = 0.f;

    #pragma unroll 4
    for (int j = 0; j < N_; j++) {
        float a[4], bb[4];
        #pragma unroll
        for (int r = 0; r < 4; r++) a[r] = Hs[(i0 + ty + 8 * r) * F_ + j];
        #pragma unroll
        for (int c = 0; c < 4; c++) bb[c] = Us[j * 128 + tx + 32 * c];
        #pragma unroll
        for (int r = 0; r < 4; r++)
            #pragma unroll
            for (int c = 0; c < 4; c++) accs[r][c] = fmaf(a[r], bb[c], accs[r][c]);
    }

    // ---- Epilogue: sigmoid(msg*D + self) ----
    #pragma unroll
    for (int r = 0; r < 4; r++) {
        int i = i0 + ty + 8 * r;
        float d = g_D[b * N_ + i];
        #pragma unroll
        for (int c = 0; c < 4; c++) {
            int n = tx + 32 * c;
            float x = accm[r][c] * d + accs[r][c];
            Hout[((size_t)b * N_ + i) * F_ + n] = 1.0f / (1.0f + expf(-x));
        }
    }
}

// ---------------------------------------------------------------------------
// MLP head: h = leaky(H3 @ W1 + b1), s = sigmoid(h @ W2 + b2), per-b partial sum
// ---------------------------------------------------------------------------
__global__ void mlp_kernel(const float* __restrict__ H3,
                           const float* __restrict__ W1,
                           const float* __restrict__ b1,
                           const float* __restrict__ W2,
                           const float* __restrict__ b2)
{
    __shared__ float W1s[F_ * 20];
    __shared__ float red[128];
    const int b = blockIdx.x;
    const int tid = threadIdx.x;   // 128 threads; thread = node row

    for (int l = tid; l < F_ * 20; l += 128) W1s[l] = W1[l];
    __syncthreads();

    const float* hrow = H3 + ((size_t)b * N_ + tid) * F_;
    float h[20];
    #pragma unroll
    for (int o = 0; o < 20; o++) h[o] = b1[o];
    for (int j = 0; j < F_; j++) {
        float hv = hrow[j];
        #pragma unroll
        for (int o = 0; o < 20; o++) h[o] = fmaf(hv, W1s[j * 20 + o], h[o]);
    }
    float z = b2[0];
    #pragma unroll
    for (int o = 0; o < 20; o++) {
        float t = h[o];
        t = fmaxf(t, 0.1f * t);    // LeakyReLU(0.1)
        z = fmaf(t, W2[o], z);
    }
    red[tid] = 1.0f / (1.0f + expf(-z));
    __syncthreads();
    #pragma unroll
    for (int o = 64; o > 0; o >>= 1) {
        if (tid < o) red[tid] += red[tid + o];
        __syncthreads();
    }
    if (tid == 0) g_part[b] = red[0];
}

__global__ void reduce_kernel(float* __restrict__ out) {
    __shared__ float red[512];
    const int tid = threadIdx.x;
    red[tid] = g_part[tid];
    __syncthreads();
    #pragma unroll
    for (int o = 256; o > 0; o >>= 1) {
        if (tid < o) red[tid] += red[tid + o];
        __syncthreads();
    }
    if (tid == 0) out[0] = red[0] / (float)(B_ * N_);
}

// ---------------------------------------------------------------------------
extern "C" void kernel_launch(void* const* d_in, const int* in_sizes, int n_in,
                              void* d_out, int out_size)
{
    const float* H   = (const float*)d_in[0];
    const float* E   = (const float*)d_in[1];
    const float* RW1 = (const float*)d_in[2];
    const float* SW1 = (const float*)d_in[3];
    const float* RW2 = (const float*)d_in[4];
    const float* SW2 = (const float*)d_in[5];
    const float* RW3 = (const float*)d_in[6];
    const float* SW3 = (const float*)d_in[7];
    const float* W1  = (const float*)d_in[8];
    const float* b1  = (const float*)d_in[9];
    const float* W2  = (const float*)d_in[10];
    const float* b2  = (const float*)d_in[11];

    float *bufA = nullptr, *bufB = nullptr;
    cudaGetSymbolAddress((void**)&bufA, g_bufA);
    cudaGetSymbolAddress((void**)&bufB, g_bufB);

    const size_t smem_bytes = 3 * 16384 * sizeof(float);  // 192 KB
    cudaFuncSetAttribute(layer_kernel, cudaFuncAttributeMaxDynamicSharedMemorySize,
                         (int)smem_bytes);

    deg_kernel<<<(B_ * N_) / 8, 256>>>(E);

    dim3 grid(NT, B_);
    layer_kernel<<<grid, 256, smem_bytes>>>(E, H,    RW1, SW1, bufA);
    layer_kernel<<<grid, 256, smem_bytes>>>(E, bufA, RW2, SW2, bufB);
    layer_kernel<<<grid, 256, smem_bytes>>>(E, bufB, RW3, SW3, bufA);

    mlp_kernel<<<B_, 128>>>(bufA, W1, b1, W2, b2);
    reduce_kernel<<<1, 512>>>((float*)d_out);
}

// round 3
// speedup vs baseline: 2.5436x; 2.5436x over previous
#include <cuda_runtime.h>
#include <cstdint>
#include <math.h>

#define B_ 512
#define N_ 128
#define F_ 128
#define K_ 4

#define FRAG_BYTES 33792   // 64 groups * 33 slots(pad) * 16B

// ---------------- device scratch (allocation-free) ----------------
__device__ float g_bufA[(size_t)B_ * N_ * F_];
__device__ float g_bufB[(size_t)B_ * N_ * F_];
__device__ float g_D[B_ * N_];
__device__ float g_part[B_];
__device__ float g_Gt[(size_t)B_ * N_ * K_ * N_];   // [b][n][k][j]
__device__ float g_RWt[3 * K_ * F_ * F_];           // [l][k][n][m] = RW[m,n,k]
__device__ float g_SWt[3 * F_ * F_];                // [l][n][j]    = SW[j,n]

// ---------------- helpers ----------------
__device__ __forceinline__ uint32_t smem_u32(const void* p) {
    uint32_t a;
    asm("{ .reg .u64 t; cvta.to.shared.u64 t, %1; cvt.u32.u64 %0, t; }" : "=r"(a) : "l"(p));
    return a;
}
__device__ __forceinline__ uint32_t cvt_tf32(float x) {
    uint32_t u; asm("cvt.rna.tf32.f32 %0, %1;" : "=r"(u) : "f"(x)); return u;
}
__device__ __forceinline__ void sts32u(uint32_t a, uint32_t v) {
    asm volatile("st.shared.b32 [%0], %1;" :: "r"(a), "r"(v));
}
__device__ __forceinline__ void sts64u(uint32_t a, uint32_t v0, uint32_t v1) {
    asm volatile("st.shared.v2.b32 [%0], {%1,%2};" :: "r"(a), "r"(v0), "r"(v1));
}
__device__ __forceinline__ void sts128u(uint32_t a, uint4 v) {
    asm volatile("st.shared.v4.b32 [%0], {%1,%2,%3,%4};" :: "r"(a), "r"(v.x), "r"(v.y), "r"(v.z), "r"(v.w));
}
__device__ __forceinline__ void lds128u(uint32_t* r, uint32_t a) {
    asm volatile("ld.shared.v4.b32 {%0,%1,%2,%3}, [%4];"
                 : "=r"(r[0]), "=r"(r[1]), "=r"(r[2]), "=r"(r[3]) : "r"(a));
}
__device__ __forceinline__ void mma8(float* c, const uint32_t* a, uint32_t b0, uint32_t b1) {
    asm volatile(
        "mma.sync.aligned.m16n8k8.row.col.f32.tf32.tf32.f32 "
        "{%0,%1,%2,%3}, {%4,%5,%6,%7}, {%8,%9}, {%0,%1,%2,%3};"
        : "+f"(c[0]), "+f"(c[1]), "+f"(c[2]), "+f"(c[3])
        : "r"(a[0]), "r"(a[1]), "r"(a[2]), "r"(a[3]), "r"(b0), "r"(b1));
}

// A-fragment scatter: value (row i, k-index kl..kl+3), optional scale, rna-converted
__device__ __forceinline__ void stageA4(uint32_t buf, int i, int kl0, float4 v, float scale) {
    uint32_t u[4] = {cvt_tf32(v.x * scale), cvt_tf32(v.y * scale),
                     cvt_tf32(v.z * scale), cvt_tf32(v.w * scale)};
    #pragma unroll
    for (int s = 0; s < 4; s++) {
        int kl = kl0 + s;
        int g = ((i >> 4) << 3) | (kl >> 3);
        int ln = ((i & 7) << 2) | (kl & 3);
        int rg = (((kl >> 2) & 1) << 1) | ((i >> 3) & 1);
        sts32u(buf + (uint32_t)(g * 33 + ln) * 16 + rg * 4, u[s]);
    }
}
// B-fragment scatter: value (col n, k-index kl..kl+3)
__device__ __forceinline__ void stageB4(uint32_t buf, int n, int kl0, float4 v) {
    uint32_t u[4] = {cvt_tf32(v.x), cvt_tf32(v.y), cvt_tf32(v.z), cvt_tf32(v.w)};
    #pragma unroll
    for (int s = 0; s < 4; s++) {
        int kl = kl0 + s;
        int g = ((n >> 3) << 2) | (kl >> 4);
        int ln = ((n & 7) << 2) | (kl & 3);
        int rg = (kl >> 2) & 3;
        sts32u(buf + (uint32_t)(g * 33 + ln) * 16 + rg * 4, u[s]);
    }
}

// ---------------------------------------------------------------------------
// Prep: RWt[l][k][n][m] = RW_l[m][n][k]; SWt[l][n][j] = SW_l[j][n]
// ---------------------------------------------------------------------------
__global__ void prep_kernel(const float* __restrict__ RW1, const float* __restrict__ SW1,
                            const float* __restrict__ RW2, const float* __restrict__ SW2,
                            const float* __restrict__ RW3, const float* __restrict__ SW3)
{
    int bid = blockIdx.x, tid = threadIdx.x;
    const float* RWs[3] = {RW1, RW2, RW3};
    const float* SWs[3] = {SW1, SW2, SW3};
    if (bid < 12) {
        int l = bid >> 2, k = bid & 3;
        const float* RW = RWs[l];
        float* dst = g_RWt + (size_t)(l * 4 + k) * 16384;
        for (int idx = tid; idx < 16384; idx += 256) {
            int n = idx >> 7, m = idx & 127;
            dst[n * 128 + m] = RW[(m * 128 + n) * 4 + k];
        }
    } else {
        int l = bid - 12;
        const float* SW = SWs[l];
        float* dst = g_SWt + (size_t)l * 16384;
        for (int idx = tid; idx < 16384; idx += 256) {
            int n = idx >> 7, j = idx & 127;
            dst[n * 128 + j] = SW[j * 128 + n];
        }
    }
}

// ---------------------------------------------------------------------------
// Degree norm
// ---------------------------------------------------------------------------
__global__ void deg_kernel(const float* __restrict__ E) {
    int warp = (blockIdx.x * blockDim.x + threadIdx.x) >> 5;
    int lane = threadIdx.x & 31;
    if (warp >= B_ * N_) return;
    const float* row = E + (size_t)warp * (N_ * K_);
    float s = 0.f;
    #pragma unroll 4
    for (int t = lane; t < N_ * K_; t += 32) s += row[t];
    #pragma unroll
    for (int o = 16; o > 0; o >>= 1) s += __shfl_xor_sync(0xffffffffu, s, o);
    if (lane == 0) g_D[warp] = 1.0f / (s + (float)K_);
}

// ---------------------------------------------------------------------------
// Kernel A: per b, for k=0..3: C[n][j] = sum_m RWt_k[n][m] * H[b][j][m]
//           write Gt[b][n][k][j] (rna'd).  mma.sync tf32 m16n8k8.
// smem: HB (2 chunk frag buffers, 67584B) | RC (RW-frag / C-bounce, 33792B)
// ---------------------------------------------------------------------------
__global__ __launch_bounds__(256, 2) void gemmG_kernel(const float* __restrict__ Hin,
                                                       const float* __restrict__ RWt,
                                                       float* __restrict__ Gt)
{
    extern __shared__ char smem[];
    uint32_t sb = smem_u32(smem);
    uint32_t HB = sb;
    uint32_t RC = sb + 2 * FRAG_BYTES;
    float* Cbuf = (float*)(smem + 2 * FRAG_BYTES);

    const int tid = threadIdx.x, wid = tid >> 5, lane = tid & 31;
    const int wy = wid >> 1, wx = wid & 1;
    const int b = blockIdx.x;

    const float4* H4 = (const float4*)(Hin + (size_t)b * 16384);
    const float4* RWt4 = (const float4*)RWt;
    float4* Gt4 = (float4*)(Gt + (size_t)b * 65536);

    // stage H (B operand, cols j, k-dim m) -- both chunks
    #pragma unroll
    for (int ch = 0; ch < 2; ch++)
        for (int l = tid; l < 2048; l += 256) {
            int j = l >> 4, q4 = l & 15;
            stageB4(HB + ch * FRAG_BYTES, j, q4 * 4, H4[j * 32 + ch * 16 + q4]);
        }

    for (int k = 0; k < K_; k++) {
        float C[2][8][4];
        #pragma unroll
        for (int m = 0; m < 2; m++)
            #pragma unroll
            for (int t = 0; t < 8; t++)
                #pragma unroll
                for (int r = 0; r < 4; r++) C[m][t][r] = 0.f;

        #pragma unroll
        for (int ch = 0; ch < 2; ch++) {
            __syncthreads();   // RC free (prev mma / prev C copy done)
            for (int l = tid; l < 2048; l += 256) {
                int n = l >> 4, q4 = l & 15;
                stageA4(RC, n, q4 * 4, RWt4[(k * 128 + n) * 32 + ch * 16 + q4], 1.f);
            }
            __syncthreads();
            uint32_t Bb = HB + ch * FRAG_BYTES;
            #pragma unroll
            for (int p = 0; p < 4; p++) {
                uint32_t bb[8][4];
                #pragma unroll
                for (int t = 0; t < 8; t++)
                    lds128u(bb[t], Bb + (uint32_t)(((((wx * 8 + t) << 2) | p) * 33 + lane)) * 16);
                #pragma unroll
                for (int h = 0; h < 2; h++) {
                    int ks = p * 2 + h;
                    uint32_t aa[2][4];
                    #pragma unroll
                    for (int m = 0; m < 2; m++)
                        lds128u(aa[m], RC + (uint32_t)(((((wy * 2 + m) << 3) | ks) * 33 + lane)) * 16);
                    #pragma unroll
                    for (int m = 0; m < 2; m++)
                        #pragma unroll
                        for (int t = 0; t < 8; t++)
                            mma8(C[m][t], aa[m], bb[t][h * 2], bb[t][h * 2 + 1]);
                }
            }
        }

        // epilogue via smem bounce (half of n rows at a time), rna'd
        const int g = lane >> 2, t2 = (lane & 3) * 2;
        #pragma unroll
        for (int hh = 0; hh < 2; hh++) {
            __syncthreads();
            if ((wy >> 1) == hh) {
                #pragma unroll
                for (int m = 0; m < 2; m++) {
                    int nl = (wy & 1) * 32 + m * 16 + g;     // row within half
                    #pragma unroll
                    for (int t = 0; t < 8; t++) {
                        int j = wx * 64 + t * 8 + t2;
                        uint32_t a0 = RC + (uint32_t)(nl * 132 + j) * 4;
                        sts64u(a0, cvt_tf32(C[m][t][0]), cvt_tf32(C[m][t][1]));
                        uint32_t a1 = RC + (uint32_t)((nl + 8) * 132 + j) * 4;
                        sts64u(a1, cvt_tf32(C[m][t][2]), cvt_tf32(C[m][t][3]));
                    }
                }
            }
            __syncthreads();
            for (int l = tid; l < 2048; l += 256) {
                int nl = l >> 5, j4 = l & 31;
                float4 v = *(const float4*)(Cbuf + nl * 132 + j4 * 4);
                Gt4[((size_t)(hh * 64 + nl) * 4 + k) * 32 + j4] = v;
            }
        }
    }
}

// ---------------------------------------------------------------------------
// Kernel B: per b, C[i][n] = sum_jk (D[i]*E[i][jk]) * Gt[b][n][jk]
//                          + sum_j  H[i][j] * SWt[n][j];  out = sigmoid(C)
// 10 chunks of K=64 (2 self + 8 msg).  smem: Dsh(512) | Afrag | Bfrag
// ---------------------------------------------------------------------------
__global__ __launch_bounds__(256, 2) void rgcn_kernel(const float* __restrict__ Hin,
                                                      const float* __restrict__ E,
                                                      const float* __restrict__ Gt,
                                                      const float* __restrict__ SWt,
                                                      float* __restrict__ Hout)
{
    extern __shared__ char smem[];
    uint32_t sb = smem_u32(smem);
    float* Dsh = (float*)smem;
    uint32_t Ab = sb + 512;
    uint32_t Bb = Ab + FRAG_BYTES;

    const int tid = threadIdx.x, wid = tid >> 5, lane = tid & 31;
    const int wy = wid >> 1, wx = wid & 1;
    const int b = blockIdx.x;

    if (tid < 128) Dsh[tid] = g_D[b * 128 + tid];
    __syncthreads();

    const float4* H4 = (const float4*)(Hin + (size_t)b * 16384);
    const float4* E4 = (const float4*)(E + (size_t)b * 65536);
    const uint4*  G4 = (const uint4*)(Gt + (size_t)b * 65536);
    const float4* S4 = (const float4*)SWt;

    float C[2][8][4];
    #pragma unroll
    for (int m = 0; m < 2; m++)
        #pragma unroll
        for (int t = 0; t < 8; t++)
            #pragma unroll
            for (int r = 0; r < 4; r++) C[m][t][r] = 0.f;

    for (int c = 0; c < 10; c++) {
        if (c < 2) {
            for (int l = tid; l < 2048; l += 256) {
                int i = l >> 4, q4 = l & 15;
                stageA4(Ab, i, q4 * 4, H4[i * 32 + c * 16 + q4], 1.f);
            }
            for (int l = tid; l < 2048; l += 256) {
                int n = l >> 4, q4 = l & 15;
                stageB4(Bb, n, q4 * 4, S4[n * 32 + c * 16 + q4]);
            }
        } else {
            int kc = c - 2;
            for (int l = tid; l < 2048; l += 256) {
                int i = l >> 4, q4 = l & 15;
                stageA4(Ab, i, q4 * 4, E4[(size_t)i * 128 + kc * 16 + q4], Dsh[i]);
            }
            for (int l = tid; l < 2048; l += 256) {
                int n = l >> 4, kq = l & 15;
                int k = kq >> 2, q = kq & 3;
                uint4 v = G4[((size_t)n * 4 + k) * 32 + kc * 4 + q];
                sts128u(Bb + (uint32_t)(((((n >> 3) << 2) | q) * 33 +
                                         (((n & 7) << 2) | k))) * 16, v);
            }
        }
        __syncthreads();
        #pragma unroll
        for (int p = 0; p < 4; p++) {
            uint32_t bb[8][4];
            #pragma unroll
            for (int t = 0; t < 8; t++)
                lds128u(bb[t], Bb + (uint32_t)(((((wx * 8 + t) << 2) | p) * 33 + lane)) * 16);
            #pragma unroll
            for (int h = 0; h < 2; h++) {
                int ks = p * 2 + h;
                uint32_t aa[2][4];
                #pragma unroll
                for (int m = 0; m < 2; m++)
                    lds128u(aa[m], Ab + (uint32_t)(((((wy * 2 + m) << 3) | ks) * 33 + lane)) * 16);
                #pragma unroll
                for (int m = 0; m < 2; m++)
                    #pragma unroll
                    for (int t = 0; t < 8; t++)
                        mma8(C[m][t], aa[m], bb[t][h * 2], bb[t][h * 2 + 1]);
            }
        }
        __syncthreads();
    }

    // epilogue: sigmoid, direct stores
    const int g = lane >> 2, t2 = (lane & 3) * 2;
    float* orow = Hout + (size_t)b * 16384;
    #pragma unroll
    for (int m = 0; m < 2; m++) {
        int i0 = wy * 32 + m * 16 + g;
        #pragma unroll
        for (int t = 0; t < 8; t++) {
            int n0 = wx * 64 + t * 8 + t2;
            orow[i0 * 128 + n0]       = 1.0f / (1.0f + expf(-C[m][t][0]));
            orow[i0 * 128 + n0 + 1]   = 1.0f / (1.0f + expf(-C[m][t][1]));
            orow[(i0 + 8) * 128 + n0]     = 1.0f / (1.0f + expf(-C[m][t][2]));
            orow[(i0 + 8) * 128 + n0 + 1] = 1.0f / (1.0f + expf(-C[m][t][3]));
        }
    }
}

// ---------------------------------------------------------------------------
// MLP head + reduce
// ---------------------------------------------------------------------------
__global__ void mlp_kernel(const float* __restrict__ H3,
                           const float* __restrict__ W1, const float* __restrict__ b1,
                           const float* __restrict__ W2, const float* __restrict__ b2)
{
    __shared__ float W1s[F_ * 20];
    __shared__ float red[128];
    const int b = blockIdx.x;
    const int tid = threadIdx.x;

    for (int l = tid; l < F_ * 20; l += 128) W1s[l] = W1[l];
    __syncthreads();

    const float* hrow = H3 + ((size_t)b * N_ + tid) * F_;
    float h[20];
    #pragma unroll
    for (int o = 0; o < 20; o++) h[o] = b1[o];
    for (int j = 0; j < F_; j++) {
        float hv = hrow[j];
        #pragma unroll
        for (int o = 0; o < 20; o++) h[o] = fmaf(hv, W1s[j * 20 + o], h[o]);
    }
    float z = b2[0];
    #pragma unroll
    for (int o = 0; o < 20; o++) {
        float t = h[o];
        t = fmaxf(t, 0.1f * t);
        z = fmaf(t, W2[o], z);
    }
    red[tid] = 1.0f / (1.0f + expf(-z));
    __syncthreads();
    #pragma unroll
    for (int o = 64; o > 0; o >>= 1) {
        if (tid < o) red[tid] += red[tid + o];
        __syncthreads();
    }
    if (tid == 0) g_part[b] = red[0];
}

__global__ void reduce_kernel(float* __restrict__ out) {
    __shared__ float red[512];
    const int tid = threadIdx.x;
    red[tid] = g_part[tid];
    __syncthreads();
    #pragma unroll
    for (int o = 256; o > 0; o >>= 1) {
        if (tid < o) red[tid] += red[tid + o];
        __syncthreads();
    }
    if (tid == 0) out[0] = red[0] / (float)(B_ * N_);
}

// ---------------------------------------------------------------------------
extern "C" void kernel_launch(void* const* d_in, const int* in_sizes, int n_in,
                              void* d_out, int out_size)
{
    const float* H   = (const float*)d_in[0];
    const float* E   = (const float*)d_in[1];
    const float* RW1 = (const float*)d_in[2];
    const float* SW1 = (const float*)d_in[3];
    const float* RW2 = (const float*)d_in[4];
    const float* SW2 = (const float*)d_in[5];
    const float* RW3 = (const float*)d_in[6];
    const float* SW3 = (const float*)d_in[7];
    const float* W1  = (const float*)d_in[8];
    const float* b1  = (const float*)d_in[9];
    const float* W2  = (const float*)d_in[10];
    const float* b2  = (const float*)d_in[11];

    float *bufA = nullptr, *bufB = nullptr, *Gt = nullptr, *RWt = nullptr, *SWt = nullptr;
    cudaGetSymbolAddress((void**)&bufA, g_bufA);
    cudaGetSymbolAddress((void**)&bufB, g_bufB);
    cudaGetSymbolAddress((void**)&Gt,   g_Gt);
    cudaGetSymbolAddress((void**)&RWt,  g_RWt);
    cudaGetSymbolAddress((void**)&SWt,  g_SWt);

    const int smemA = 2 * FRAG_BYTES + FRAG_BYTES;        // 101376
    const int smemB = 512 + 2 * FRAG_BYTES;               // 68096
    cudaFuncSetAttribute(gemmG_kernel, cudaFuncAttributeMaxDynamicSharedMemorySize, smemA);
    cudaFuncSetAttribute(rgcn_kernel,  cudaFuncAttributeMaxDynamicSharedMemorySize, smemB);

    prep_kernel<<<15, 256>>>(RW1, SW1, RW2, SW2, RW3, SW3);
    deg_kernel<<<(B_ * N_) / 8, 256>>>(E);

    gemmG_kernel<<<B_, 256, smemA>>>(H, RWt + 0 * K_ * F_ * F_, Gt);
    rgcn_kernel<<<B_, 256, smemB>>>(H, E, Gt, SWt + 0 * F_ * F_, bufA);

    gemmG_kernel<<<B_, 256, smemA>>>(bufA, RWt + 1 * K_ * F_ * F_, Gt);
    rgcn_kernel<<<B_, 256, smemB>>>(bufA, E, Gt, SWt + 1 * F_ * F_, bufB);

    gemmG_kernel<<<B_, 256, smemA>>>(bufB, RWt + 2 * K_ * F_ * F_, Gt);
    rgcn_kernel<<<B_, 256, smemB>>>(bufB, E, Gt, SWt + 2 * F_ * F_, bufA);

    mlp_kernel<<<B_, 128>>>(bufA, W1, b1, W2, b2);
    reduce_kernel<<<1, 512>>>((float*)d_out);
}